// round 1
// baseline (speedup 1.0000x reference)
#include <cuda_runtime.h>

// ---------------------------------------------------------------------------
// DifferentiableEditLayer: B=8, C=3, H=1024, W=1536 fp32 image edit pipeline.
// 5 kernels: base+luma0+mask_h reduce, 3 sequential region-mask reduces,
// final fused per-pixel pass. Scratch in __device__ globals (no allocs).
// ---------------------------------------------------------------------------

namespace {
constexpr int NB  = 8;
constexpr int Hc  = 1024;
constexpr int Wc  = 1536;
constexpr int HW  = Hc * Wc;        // 1572864
constexpr int HW4 = HW / 4;         // 393216
constexpr int NT  = 256;
constexpr int BPB = 192;            // blocks per batch (HW4 = 8 * BPB * NT exactly)
}

__device__ float g_luma[NB * HW];           // luma0 after base transform
__device__ float g_part[4][NB][BPB];        // per-block partial mask sums

__device__ __forceinline__ float clip01(float x) { return fminf(fmaxf(x, 0.0f), 1.0f); }
__device__ __forceinline__ float clip04(float x) { return fminf(fmaxf(x, 0.0f), 4.0f); }
__device__ __forceinline__ float sigm(float x)   { return __fdividef(1.0f, 1.0f + __expf(-x)); }
__device__ __forceinline__ float lum3(float r, float g, float b) {
    return 0.2126f * r + 0.7152f * g + 0.0722f * b;
}

// Deterministic block tree-reduction (fixed order -> bit-stable across replays).
__device__ __forceinline__ float block_reduce(float v, float* sh) {
    const int tid = threadIdx.x;
    sh[tid] = v;
    __syncthreads();
    #pragma unroll
    for (int s = NT / 2; s > 0; s >>= 1) {
        if (tid < s) sh[tid] += sh[tid + s];
        __syncthreads();
    }
    float t = sh[0];
    __syncthreads();
    return t;
}

struct BaseParams { float gr, gg, gb, expo, cf; };

__device__ __forceinline__ BaseParams make_base(const float* tn, const float* tin,
                                                const float* en, const float* cn, int b) {
    float tempv = 2000.0f + 0.5f * (tn[b] + 1.0f) * 48000.0f;
    tempv = fminf(fmaxf(tempv, 2000.0f), 50000.0f);
    float tr = __fdividef(6500.0f, tempv);
    float s  = sqrtf(tr);
    float tintv = -150.0f + 0.5f * (tin[b] + 1.0f) * 300.0f;
    float ts = fminf(fmaxf(tintv * (1.0f / 150.0f), -1.5f), 1.5f);
    float red   = s * (1.0f + 0.05f * ts);
    float green = 1.0f - 0.1f * ts;
    float blue  = __fdividef(1.0f, s) * (1.0f - 0.05f * ts);
    float nrm = fmaxf(red, fmaxf(green, blue));
    float inv = __fdividef(1.0f, fmaxf(nrm, 1e-4f));
    BaseParams p;
    p.gr = red * inv; p.gg = green * inv; p.gb = blue * inv;
    float ev = -5.0f + 0.5f * (en[b] + 1.0f) * 10.0f;
    p.expo = exp2f(ev);
    float cv = -100.0f + 0.5f * (cn[b] + 1.0f) * 200.0f;
    p.cf = 1.0f + cv * 0.01f;
    return p;
}

__device__ __forceinline__ void base_px(float& r, float& g, float& b, const BaseParams& p) {
    r = clip01(r); g = clip01(g); b = clip01(b);
    r = clip04(r * p.gr); g = clip04(g * p.gg); b = clip04(b * p.gb);
    r = clip04(r * p.expo); g = clip04(g * p.expo); b = clip04(b * p.expo);
    r = clip01((r - 0.5f) * p.cf + 0.5f);
    g = clip01((g - 0.5f) * p.cf + 0.5f);
    b = clip01((b - 0.5f) * p.cf + 0.5f);
}

__device__ __forceinline__ float region_strength(const float* sl, int b) {
    float v = -100.0f + 0.5f * (sl[b] + 1.0f) * 200.0f;   // denorm
    return v * 0.01f;                                      // /100
}

// ---------------------------------------------------------------------------
// Kernel 1: base transform, write luma0, reduce highlights mask sum.
// ---------------------------------------------------------------------------
__global__ void __launch_bounds__(NT) k_pre(
    const float* __restrict__ img,
    const float* __restrict__ tn, const float* __restrict__ tin,
    const float* __restrict__ en, const float* __restrict__ cn)
{
    __shared__ float sh[NT];
    const int b = blockIdx.y;
    const BaseParams p = make_base(tn, tin, en, cn, b);
    const float* base = img + (size_t)b * 3 * HW;
    float* lbase = g_luma + (size_t)b * HW;
    float sum = 0.0f;
    for (int q = blockIdx.x * NT + threadIdx.x; q < HW4; q += BPB * NT) {
        const int idx = q * 4;
        float4 R  = *reinterpret_cast<const float4*>(base + idx);
        float4 G  = *reinterpret_cast<const float4*>(base + HW + idx);
        float4 Bv = *reinterpret_cast<const float4*>(base + 2 * HW + idx);
        float r[4]  = {R.x, R.y, R.z, R.w};
        float g[4]  = {G.x, G.y, G.z, G.w};
        float bl[4] = {Bv.x, Bv.y, Bv.z, Bv.w};
        float4 L;
        float* lp = &L.x;
        #pragma unroll
        for (int i = 0; i < 4; i++) {
            base_px(r[i], g[i], bl[i], p);
            float l = clip01(lum3(r[i], g[i], bl[i]));
            lp[i] = l;
            sum += sigm((l - 0.7f) * 10.0f);
        }
        *reinterpret_cast<float4*>(lbase + idx) = L;
    }
    float tot = block_reduce(sum, sh);
    if (threadIdx.x == 0) g_part[0][b][blockIdx.x] = tot;
}

// ---------------------------------------------------------------------------
// Kernels 2-4: chain luma through S prior regions, reduce mask S sum.
// ---------------------------------------------------------------------------
template <int S>
__global__ void __launch_bounds__(NT) k_region(
    const float* __restrict__ hn, const float* __restrict__ sn,
    const float* __restrict__ wn, const float* __restrict__ bn)
{
    __shared__ float sh[NT];
    const int b = blockIdx.y;
    const float piv[4]  = {0.7f, 0.3f, 0.9f, 0.1f};
    const float invw[4] = {1.0f / 0.1f, 1.0f / 0.12f, 1.0f / 0.08f, 1.0f / 0.08f};
    const float str[4]  = {region_strength(hn, b), region_strength(sn, b),
                           region_strength(wn, b), region_strength(bn, b)};
    float mean[4];
    #pragma unroll
    for (int k = 0; k < S; k++) {
        float v = (threadIdx.x < BPB) ? g_part[k][b][threadIdx.x] : 0.0f;
        mean[k] = block_reduce(v, sh) / (float)HW;
    }
    const float* lbase = g_luma + (size_t)b * HW;
    float sum = 0.0f;
    for (int q = blockIdx.x * NT + threadIdx.x; q < HW4; q += BPB * NT) {
        float4 L = *reinterpret_cast<const float4*>(lbase + q * 4);
        float lv[4] = {L.x, L.y, L.z, L.w};
        #pragma unroll
        for (int i = 0; i < 4; i++) {
            float l = lv[i];
            #pragma unroll
            for (int k = 0; k < S; k++)
                l = clip01(l + str[k] * (sigm((l - piv[k]) * invw[k]) - mean[k]));
            sum += sigm((l - piv[S]) * invw[S]);
        }
    }
    float tot = block_reduce(sum, sh);
    if (threadIdx.x == 0) g_part[S][b][blockIdx.x] = tot;
}

// ---------------------------------------------------------------------------
// Kernel 5: full fused per-pixel pipeline, writes output.
// ---------------------------------------------------------------------------
__global__ void __launch_bounds__(NT) k_final(
    const float* __restrict__ img, const float* __restrict__ tc,
    const float* __restrict__ tn, const float* __restrict__ tin,
    const float* __restrict__ en, const float* __restrict__ cn,
    const float* __restrict__ hn, const float* __restrict__ sn,
    const float* __restrict__ wn, const float* __restrict__ bn,
    const float* __restrict__ vn, const float* __restrict__ satn,
    float* __restrict__ out)
{
    __shared__ float sh[NT];
    __shared__ float curve[1024];
    const int b = blockIdx.y;
    const int tid = threadIdx.x;

    float mean[4];
    #pragma unroll
    for (int k = 0; k < 4; k++) {
        float v = (tid < BPB) ? g_part[k][b][tid] : 0.0f;
        mean[k] = block_reduce(v, sh) / (float)HW;
    }

    // Build 1024-entry per-batch tone curve in shared memory (align_corners).
    const float* tcb = tc + b * 256;
    for (int j = tid; j < 1024; j += NT) {
        float src = (float)j * (255.0f / 1023.0f);
        int i0 = (int)src;
        int i1 = min(i0 + 1, 255);
        float w = src - (float)i0;
        curve[j] = tcb[i0] * (1.0f - w) + tcb[i1] * w;
    }

    const BaseParams p = make_base(tn, tin, en, cn, b);
    const float piv[4]  = {0.7f, 0.3f, 0.9f, 0.1f};
    const float invw[4] = {1.0f / 0.1f, 1.0f / 0.12f, 1.0f / 0.08f, 1.0f / 0.08f};
    const float str[4]  = {region_strength(hn, b), region_strength(sn, b),
                           region_strength(wn, b), region_strength(bn, b)};
    const float vib  = (-100.0f + 0.5f * (vn[b] + 1.0f) * 200.0f) * 0.01f;
    const float satg = 1.0f + (-100.0f + 0.5f * (satn[b] + 1.0f) * 200.0f) * 0.01f;
    __syncthreads();

    const float* base  = img + (size_t)b * 3 * HW;
    float*       obase = out + (size_t)b * 3 * HW;
    for (int q = blockIdx.x * NT + tid; q < HW4; q += BPB * NT) {
        const int idx = q * 4;
        float4 R  = *reinterpret_cast<const float4*>(base + idx);
        float4 G  = *reinterpret_cast<const float4*>(base + HW + idx);
        float4 Bv = *reinterpret_cast<const float4*>(base + 2 * HW + idx);
        float r[4]  = {R.x, R.y, R.z, R.w};
        float g[4]  = {G.x, G.y, G.z, G.w};
        float bl[4] = {Bv.x, Bv.y, Bv.z, Bv.w};
        #pragma unroll
        for (int i = 0; i < 4; i++) {
            float rr = r[i], gg = g[i], bb = bl[i];
            base_px(rr, gg, bb, p);
            float l = clip01(lum3(rr, gg, bb));
            // 4 region stages
            #pragma unroll
            for (int k = 0; k < 4; k++) {
                float nl = clip01(l + str[k] * (sigm((l - piv[k]) * invw[k]) - mean[k]));
                float ratio = (l > 1e-4f) ? __fdividef(nl, fmaxf(l, 1e-4f)) : 1.0f;
                rr = clip01(rr * ratio);
                gg = clip01(gg * ratio);
                bb = clip01(bb * ratio);
                l = nl;
            }
            // tone curve
            {
                float lt = clip01(lum3(rr, gg, bb));
                float c = lt * 1023.0f;
                int lo = (int)c;
                int hi = min(lo + 1, 1023);
                float wt = c - (float)lo;
                float target = curve[lo] * (1.0f - wt) + curve[hi] * wt;
                float ratio = (lt > 1e-5f) ? __fdividef(target, fmaxf(lt, 1e-5f)) : 1.0f;
                rr = clip01(rr * ratio);
                gg = clip01(gg * ratio);
                bb = clip01(bb * ratio);
            }
            // vibrance
            {
                float lv = lum3(rr, gg, bb);
                float cr = rr - lv, cg = gg - lv, cb = bb - lv;
                float cnorm = sqrtf(cr * cr + cg * cg + cb * cb + 1e-6f);
                float gmask = __expf(-4.0f * cnorm);
                float gain = fminf(fmaxf(1.0f + vib * gmask, 0.2f), 4.0f);
                rr = clip01(lv + cr * gain);
                gg = clip01(lv + cg * gain);
                bb = clip01(lv + cb * gain);
            }
            // saturation (output already clipped to [0,1] -> final clip is no-op)
            {
                float lv = lum3(rr, gg, bb);
                rr = clip01(lv + (rr - lv) * satg);
                gg = clip01(lv + (gg - lv) * satg);
                bb = clip01(lv + (bb - lv) * satg);
            }
            r[i] = rr; g[i] = gg; bl[i] = bb;
        }
        *reinterpret_cast<float4*>(obase + idx)          = make_float4(r[0], r[1], r[2], r[3]);
        *reinterpret_cast<float4*>(obase + HW + idx)     = make_float4(g[0], g[1], g[2], g[3]);
        *reinterpret_cast<float4*>(obase + 2 * HW + idx) = make_float4(bl[0], bl[1], bl[2], bl[3]);
    }
}

// ---------------------------------------------------------------------------
extern "C" void kernel_launch(void* const* d_in, const int* in_sizes, int n_in,
                              void* d_out, int out_size) {
    const float* image = (const float*)d_in[0];
    const float* tone  = (const float*)d_in[1];
    const float* tempn = (const float*)d_in[2];
    const float* tintn = (const float*)d_in[3];
    const float* expn  = (const float*)d_in[4];
    const float* conn  = (const float*)d_in[5];
    const float* hin   = (const float*)d_in[6];
    const float* shn   = (const float*)d_in[7];
    const float* whn   = (const float*)d_in[8];
    const float* bln   = (const float*)d_in[9];
    const float* vin   = (const float*)d_in[10];
    const float* san   = (const float*)d_in[11];
    float* out = (float*)d_out;

    dim3 grid(BPB, NB);
    k_pre<<<grid, NT>>>(image, tempn, tintn, expn, conn);
    k_region<1><<<grid, NT>>>(hin, shn, whn, bln);
    k_region<2><<<grid, NT>>>(hin, shn, whn, bln);
    k_region<3><<<grid, NT>>>(hin, shn, whn, bln);
    k_final<<<grid, NT>>>(image, tone, tempn, tintn, expn, conn,
                          hin, shn, whn, bln, vin, san, out);
}

// round 2
// speedup vs baseline: 1.1939x; 1.1939x over previous
#include <cuda_runtime.h>

// ---------------------------------------------------------------------------
// DifferentiableEditLayer: B=8, C=3, H=1024, W=1536 fp32 image edit pipeline.
// R2: region mask means via 4096-bin luma histogram (integer, deterministic)
// instead of 3 full-image MUFU-bound sweeps.
// Kernels: k_pre (base+histogram), k_hsum (hist reduce), k_means (chain means
// on bins), k_final (fused per-pixel output pass).
// ---------------------------------------------------------------------------

namespace {
constexpr int NB   = 8;
constexpr int Hc   = 1024;
constexpr int Wc   = 1536;
constexpr int HW   = Hc * Wc;        // 1572864
constexpr int HW4  = HW / 4;         // 393216
constexpr int NT   = 256;
constexpr int BPRE = 64;             // k_pre blocks per batch
constexpr int BPB  = 192;            // k_final blocks per batch
constexpr int NBINS = 4096;
}

// Scratch (static device globals; no allocations).
__device__ unsigned int g_bhc[NB][BPRE][NBINS];   // per-block bin counts
__device__ int          g_bhr[NB][BPRE][NBINS];   // per-block residual sums (l*4095-idx)*65536
__device__ unsigned int g_hc[NB][NBINS];          // reduced counts
__device__ long long    g_hr[NB][NBINS];          // reduced residuals
__device__ float        g_mean[4][NB];            // region mask means

__device__ __forceinline__ float clip01(float x) { return fminf(fmaxf(x, 0.0f), 1.0f); }
__device__ __forceinline__ float clip04(float x) { return fminf(fmaxf(x, 0.0f), 4.0f); }
__device__ __forceinline__ float sigm(float x)   { return __fdividef(1.0f, 1.0f + __expf(-x)); }
__device__ __forceinline__ float lum3(float r, float g, float b) {
    return 0.2126f * r + 0.7152f * g + 0.0722f * b;
}

__device__ __forceinline__ float block_reduce(float v, float* sh) {
    const int tid = threadIdx.x;
    sh[tid] = v;
    __syncthreads();
    #pragma unroll
    for (int s = NT / 2; s > 0; s >>= 1) {
        if (tid < s) sh[tid] += sh[tid + s];
        __syncthreads();
    }
    float t = sh[0];
    __syncthreads();
    return t;
}

struct BaseParams { float gr, gg, gb, expo, cf; };

__device__ __forceinline__ BaseParams make_base(const float* tn, const float* tin,
                                                const float* en, const float* cn, int b) {
    float tempv = 2000.0f + 0.5f * (tn[b] + 1.0f) * 48000.0f;
    tempv = fminf(fmaxf(tempv, 2000.0f), 50000.0f);
    float tr = __fdividef(6500.0f, tempv);
    float s  = sqrtf(tr);
    float tintv = -150.0f + 0.5f * (tin[b] + 1.0f) * 300.0f;
    float ts = fminf(fmaxf(tintv * (1.0f / 150.0f), -1.5f), 1.5f);
    float red   = s * (1.0f + 0.05f * ts);
    float green = 1.0f - 0.1f * ts;
    float blue  = __fdividef(1.0f, s) * (1.0f - 0.05f * ts);
    float nrm = fmaxf(red, fmaxf(green, blue));
    float inv = __fdividef(1.0f, fmaxf(nrm, 1e-4f));
    BaseParams p;
    p.gr = red * inv; p.gg = green * inv; p.gb = blue * inv;
    float ev = -5.0f + 0.5f * (en[b] + 1.0f) * 10.0f;
    p.expo = exp2f(ev);
    float cv = -100.0f + 0.5f * (cn[b] + 1.0f) * 200.0f;
    p.cf = 1.0f + cv * 0.01f;
    return p;
}

__device__ __forceinline__ void base_px(float& r, float& g, float& b, const BaseParams& p) {
    r = clip01(r); g = clip01(g); b = clip01(b);
    r = clip04(r * p.gr); g = clip04(g * p.gg); b = clip04(b * p.gb);
    r = clip04(r * p.expo); g = clip04(g * p.expo); b = clip04(b * p.expo);
    r = clip01((r - 0.5f) * p.cf + 0.5f);
    g = clip01((g - 0.5f) * p.cf + 0.5f);
    b = clip01((b - 0.5f) * p.cf + 0.5f);
}

__device__ __forceinline__ float region_strength(const float* sl, int b) {
    float v = -100.0f + 0.5f * (sl[b] + 1.0f) * 200.0f;
    return v * 0.01f;
}

// ---------------------------------------------------------------------------
// Kernel 1: base transform -> luma0 -> per-block histogram (count + residual).
// Align-corners binning: idx = round(l * (NBINS-1)); l==0 and l==1 exact.
// ---------------------------------------------------------------------------
__global__ void __launch_bounds__(NT) k_pre(
    const float* __restrict__ img,
    const float* __restrict__ tn, const float* __restrict__ tin,
    const float* __restrict__ en, const float* __restrict__ cn)
{
    __shared__ unsigned int shc[NBINS];
    __shared__ int          shr[NBINS];
    const int b = blockIdx.y;
    const int tid = threadIdx.x;
    for (int j = tid; j < NBINS; j += NT) { shc[j] = 0u; shr[j] = 0; }
    __syncthreads();

    const BaseParams p = make_base(tn, tin, en, cn, b);
    const float* base = img + (size_t)b * 3 * HW;
    for (int q = blockIdx.x * NT + tid; q < HW4; q += BPRE * NT) {
        const int idx = q * 4;
        float4 R  = *reinterpret_cast<const float4*>(base + idx);
        float4 G  = *reinterpret_cast<const float4*>(base + HW + idx);
        float4 Bv = *reinterpret_cast<const float4*>(base + 2 * HW + idx);
        float r[4]  = {R.x, R.y, R.z, R.w};
        float g[4]  = {G.x, G.y, G.z, G.w};
        float bl[4] = {Bv.x, Bv.y, Bv.z, Bv.w};
        #pragma unroll
        for (int i = 0; i < 4; i++) {
            base_px(r[i], g[i], bl[i], p);
            float l = clip01(lum3(r[i], g[i], bl[i]));
            float scaled = l * (float)(NBINS - 1);
            int bin = __float2int_rn(scaled);
            int res = __float2int_rn((scaled - (float)bin) * 65536.0f);
            atomicAdd(&shc[bin], 1u);
            atomicAdd(&shr[bin], res);
        }
    }
    __syncthreads();
    for (int j = tid; j < NBINS; j += NT) {
        g_bhc[b][blockIdx.x][j] = shc[j];
        g_bhr[b][blockIdx.x][j] = shr[j];
    }
}

// ---------------------------------------------------------------------------
// Kernel 2: reduce per-block histograms -> g_hc / g_hr (fixed order).
// grid (NBINS/NT, NB); thread owns one bin.
// ---------------------------------------------------------------------------
__global__ void __launch_bounds__(NT) k_hsum()
{
    const int b = blockIdx.y;
    const int bin = blockIdx.x * NT + threadIdx.x;
    unsigned int c = 0u;
    long long    r = 0;
    #pragma unroll 4
    for (int k = 0; k < BPRE; k++) {
        c += g_bhc[b][k][bin];
        r += (long long)g_bhr[b][k][bin];
    }
    g_hc[b][bin] = c;
    g_hr[b][bin] = r;
}

// ---------------------------------------------------------------------------
// Kernel 3: chain the 4 region mask means over the 4096-bin histogram.
// One block per batch; deterministic tree reductions.
// ---------------------------------------------------------------------------
__global__ void __launch_bounds__(NT) k_means(
    const float* __restrict__ hn, const float* __restrict__ sn,
    const float* __restrict__ wn, const float* __restrict__ bn)
{
    __shared__ float sh[NT];
    const int b = blockIdx.x;
    const int tid = threadIdx.x;
    constexpr int PB = NBINS / NT;   // 16 bins per thread

    const float piv[4]  = {0.7f, 0.3f, 0.9f, 0.1f};
    const float invw[4] = {1.0f / 0.1f, 1.0f / 0.12f, 1.0f / 0.08f, 1.0f / 0.08f};
    const float str[4]  = {region_strength(hn, b), region_strength(sn, b),
                           region_strength(wn, b), region_strength(bn, b)};

    float lv[PB];
    float cf[PB];
    #pragma unroll
    for (int t = 0; t < PB; t++) {
        int j = tid + t * NT;
        unsigned int c = g_hc[b][j];
        cf[t] = (float)c;
        if (c > 0u) {
            double lm = ((double)j + (double)g_hr[b][j] / (65536.0 * (double)c))
                        * (1.0 / (double)(NBINS - 1));
            lv[t] = (float)lm;
        } else {
            lv[t] = 0.0f;
        }
    }

    #pragma unroll
    for (int k = 0; k < 4; k++) {
        float s[PB];
        float partial = 0.0f;
        #pragma unroll
        for (int t = 0; t < PB; t++) {
            s[t] = sigm((lv[t] - piv[k]) * invw[k]);
            partial += cf[t] * s[t];
        }
        float m = block_reduce(partial, sh) * (1.0f / (float)HW);
        if (tid == 0) g_mean[k][b] = m;
        #pragma unroll
        for (int t = 0; t < PB; t++)
            lv[t] = clip01(lv[t] + str[k] * (s[t] - m));
    }
}

// ---------------------------------------------------------------------------
// Kernel 4: full fused per-pixel pipeline, writes output.
// ---------------------------------------------------------------------------
__global__ void __launch_bounds__(NT) k_final(
    const float* __restrict__ img, const float* __restrict__ tc,
    const float* __restrict__ tn, const float* __restrict__ tin,
    const float* __restrict__ en, const float* __restrict__ cn,
    const float* __restrict__ hn, const float* __restrict__ sn,
    const float* __restrict__ wn, const float* __restrict__ bn,
    const float* __restrict__ vn, const float* __restrict__ satn,
    float* __restrict__ out)
{
    __shared__ float curve[1024];
    const int b = blockIdx.y;
    const int tid = threadIdx.x;

    float mean[4];
    #pragma unroll
    for (int k = 0; k < 4; k++) mean[k] = g_mean[k][b];

    // 1024-entry per-batch tone curve in shared memory (align_corners).
    const float* tcb = tc + b * 256;
    for (int j = tid; j < 1024; j += NT) {
        float src = (float)j * (255.0f / 1023.0f);
        int i0 = (int)src;
        int i1 = min(i0 + 1, 255);
        float w = src - (float)i0;
        curve[j] = tcb[i0] * (1.0f - w) + tcb[i1] * w;
    }

    const BaseParams p = make_base(tn, tin, en, cn, b);
    const float piv[4]  = {0.7f, 0.3f, 0.9f, 0.1f};
    const float invw[4] = {1.0f / 0.1f, 1.0f / 0.12f, 1.0f / 0.08f, 1.0f / 0.08f};
    const float str[4]  = {region_strength(hn, b), region_strength(sn, b),
                           region_strength(wn, b), region_strength(bn, b)};
    const float vib  = (-100.0f + 0.5f * (vn[b] + 1.0f) * 200.0f) * 0.01f;
    const float satg = 1.0f + (-100.0f + 0.5f * (satn[b] + 1.0f) * 200.0f) * 0.01f;
    __syncthreads();

    const float* base  = img + (size_t)b * 3 * HW;
    float*       obase = out + (size_t)b * 3 * HW;
    for (int q = blockIdx.x * NT + tid; q < HW4; q += BPB * NT) {
        const int idx = q * 4;
        float4 R  = *reinterpret_cast<const float4*>(base + idx);
        float4 G  = *reinterpret_cast<const float4*>(base + HW + idx);
        float4 Bv = *reinterpret_cast<const float4*>(base + 2 * HW + idx);
        float r[4]  = {R.x, R.y, R.z, R.w};
        float g[4]  = {G.x, G.y, G.z, G.w};
        float bl[4] = {Bv.x, Bv.y, Bv.z, Bv.w};
        #pragma unroll
        for (int i = 0; i < 4; i++) {
            float rr = r[i], gg = g[i], bb = bl[i];
            base_px(rr, gg, bb, p);
            float l = clip01(lum3(rr, gg, bb));
            // 4 region stages
            #pragma unroll
            for (int k = 0; k < 4; k++) {
                float nl = clip01(l + str[k] * (sigm((l - piv[k]) * invw[k]) - mean[k]));
                float ratio = (l > 1e-4f) ? __fdividef(nl, fmaxf(l, 1e-4f)) : 1.0f;
                rr = clip01(rr * ratio);
                gg = clip01(gg * ratio);
                bb = clip01(bb * ratio);
                l = nl;
            }
            // tone curve
            {
                float lt = clip01(lum3(rr, gg, bb));
                float c = lt * 1023.0f;
                int lo = (int)c;
                int hi = min(lo + 1, 1023);
                float wt = c - (float)lo;
                float target = curve[lo] * (1.0f - wt) + curve[hi] * wt;
                float ratio = (lt > 1e-5f) ? __fdividef(target, fmaxf(lt, 1e-5f)) : 1.0f;
                rr = clip01(rr * ratio);
                gg = clip01(gg * ratio);
                bb = clip01(bb * ratio);
            }
            // vibrance
            {
                float lv = lum3(rr, gg, bb);
                float cr = rr - lv, cg = gg - lv, cb = bb - lv;
                float cnorm = sqrtf(cr * cr + cg * cg + cb * cb + 1e-6f);
                float gmask = __expf(-4.0f * cnorm);
                float gain = fminf(fmaxf(1.0f + vib * gmask, 0.2f), 4.0f);
                rr = clip01(lv + cr * gain);
                gg = clip01(lv + cg * gain);
                bb = clip01(lv + cb * gain);
            }
            // saturation
            {
                float lv = lum3(rr, gg, bb);
                rr = clip01(lv + (rr - lv) * satg);
                gg = clip01(lv + (gg - lv) * satg);
                bb = clip01(lv + (bb - lv) * satg);
            }
            r[i] = rr; g[i] = gg; bl[i] = bb;
        }
        *reinterpret_cast<float4*>(obase + idx)          = make_float4(r[0], r[1], r[2], r[3]);
        *reinterpret_cast<float4*>(obase + HW + idx)     = make_float4(g[0], g[1], g[2], g[3]);
        *reinterpret_cast<float4*>(obase + 2 * HW + idx) = make_float4(bl[0], bl[1], bl[2], bl[3]);
    }
}

// ---------------------------------------------------------------------------
extern "C" void kernel_launch(void* const* d_in, const int* in_sizes, int n_in,
                              void* d_out, int out_size) {
    const float* image = (const float*)d_in[0];
    const float* tone  = (const float*)d_in[1];
    const float* tempn = (const float*)d_in[2];
    const float* tintn = (const float*)d_in[3];
    const float* expn  = (const float*)d_in[4];
    const float* conn  = (const float*)d_in[5];
    const float* hin   = (const float*)d_in[6];
    const float* shn   = (const float*)d_in[7];
    const float* whn   = (const float*)d_in[8];
    const float* bln   = (const float*)d_in[9];
    const float* vin   = (const float*)d_in[10];
    const float* san   = (const float*)d_in[11];
    float* out = (float*)d_out;

    k_pre<<<dim3(BPRE, NB), NT>>>(image, tempn, tintn, expn, conn);
    k_hsum<<<dim3(NBINS / NT, NB), NT>>>();
    k_means<<<NB, NT>>>(hin, shn, whn, bln);
    k_final<<<dim3(BPB, NB), NT>>>(image, tone, tempn, tintn, expn, conn,
                                   hin, shn, whn, bln, vin, san, out);
}